// round 16
// baseline (speedup 1.0000x reference)
#include <cuda_runtime.h>
#include <cuda_fp16.h>
#include <cstdint>

// Conv2d 3x3 s1 p1 via mma.sync m16n8k16 FP16 (f32 accum) implicit GEMM.
// 128-thread CTAs, CTA tile 128oc x 80px, 4 warps of 64x40 -> ~160 regs ->
// 3 CTAs/SM (12 warps, 3/SMSP) for latency hiding. K order: chunk(64ch), tap,
// k16; per chunk one union window (32 cpairs x 296 words) staged once via
// cp.async; both chunks staged upfront; 2 syncs per CTA.

#define HW    3136
#define PHW   3364            // 58*58
#define CIN   128
#define COUT  256
#define KTOT  1152
#define LDW   296             // window row stride (words); 296 mod 32 = 8
#define WCOLS 74              // cp16 per staged row (296 words)
#define CHUNKW (32*LDW)       // 9472 words per chunk window
#define SMEM_BYTES ((2*CHUNKW + 16)*4)   // 75840 B  (x3 CTAs = 227.5KB/SM)

#define WF_WORDS  (72*2*2*32*16)         // 147456
#define WF_BLOCKS (WF_WORDS/256)         // 576
#define XH_ITEMS  (32*64*56*14)
#define XH_BLOCKS (XH_ITEMS/256)         // 6272

__device__ __align__(16) uint32_t g_wf[WF_WORDS];
__device__ __align__(16) uint32_t g_xh[32 * 64 * PHW + 1024];

// wf word w: reg=w&3, mf=(w>>2)&3, lane=(w>>4)&31, wmg=(w>>9)&1, oct=(w>>10)&1,
//            kt16=w>>11 ; kt16 = chunk*36 + tap*4 + h ; c = chunk*64+h*16+klocal
__global__ void prep_kernel(const float* __restrict__ W, const float* __restrict__ x) {
    if (blockIdx.x < WF_BLOCKS) {
        const int w = blockIdx.x * 256 + threadIdx.x;
        const int reg = w & 3, mf = (w >> 2) & 3, lane = (w >> 4) & 31;
        const int wmg = (w >> 9) & 1, oct = (w >> 10) & 1, kt = w >> 11;
        const int chunk = kt / 36, rem = kt - chunk * 36;
        const int tap = rem >> 2, h = rem & 3;
        const int r = lane >> 2, cq = lane & 3;
        const int oc = oct * 128 + wmg * 64 + mf * 16 + r + (reg & 1) * 8;
        const int klocal = 2 * cq + ((reg & 2) ? 8 : 0);
        const int c = chunk * 64 + h * 16 + klocal;
        const __half2 hv = __floats2half2_rn(W[oc * KTOT + c * 9 + tap],
                                             W[oc * KTOT + (c + 1) * 9 + tap]);
        g_wf[w] = *reinterpret_cast<const uint32_t*>(&hv);
    } else {
        const int item = (blockIdx.x - WF_BLOCKS) * 256 + threadIdx.x;
        const int g = item % 14;
        const int t = item / 14;
        const int ph = t % 56;
        const int cpni = t / 56;
        const float* src = x + (size_t)2 * cpni * HW + ph * 56 + 4 * g;
        const float4 lo = __ldg(reinterpret_cast<const float4*>(src));
        const float4 hi = __ldg(reinterpret_cast<const float4*>(src + HW));
        uint32_t* dst = g_xh + (size_t)cpni * PHW + (ph + 1) * 58 + 1 + 4 * g;
        __half2 h0 = __floats2half2_rn(lo.x, hi.x);
        __half2 h1 = __floats2half2_rn(lo.y, hi.y);
        __half2 h2 = __floats2half2_rn(lo.z, hi.z);
        __half2 h3 = __floats2half2_rn(lo.w, hi.w);
        dst[0] = *reinterpret_cast<const uint32_t*>(&h0);
        dst[1] = *reinterpret_cast<const uint32_t*>(&h1);
        dst[2] = *reinterpret_cast<const uint32_t*>(&h2);
        dst[3] = *reinterpret_cast<const uint32_t*>(&h3);
    }
}

__device__ __forceinline__ void cp16(uint32_t d, const void* s) {
    asm volatile("cp.async.cg.shared.global [%0], [%1], 16;" :: "r"(d), "l"(s));
}
#define CP_COMMIT asm volatile("cp.async.commit_group;" ::: "memory")
#define CP_WAIT(n) asm volatile("cp.async.wait_group %0;" :: "n"(n) : "memory")

#define MMA16(acc, a, b0, b1) \
    asm volatile("mma.sync.aligned.m16n8k16.row.col.f32.f16.f16.f32 " \
        "{%0,%1,%2,%3}, {%4,%5,%6,%7}, {%8,%9}, {%0,%1,%2,%3};" \
        : "+f"((acc)[0]), "+f"((acc)[1]), "+f"((acc)[2]), "+f"((acc)[3]) \
        : "r"((a)[0]), "r"((a)[1]), "r"((a)[2]), "r"((a)[3]), "r"(b0), "r"(b1))

__global__ void __launch_bounds__(128, 3)
conv_mma(const float* __restrict__ bias, float* __restrict__ out)
{
    extern __shared__ uint32_t smW[];
    const uint32_t smb = (uint32_t)__cvta_generic_to_shared(smW);
    const int tid  = threadIdx.x;
    const int lane = tid & 31;
    const int wid  = tid >> 5;
    const int r    = lane >> 2, cq = lane & 3;
    const int p0   = blockIdx.x * 80;      // 80-px tile
    const int ni   = blockIdx.y;
    const int oct  = blockIdx.z;
    const int wmg  = wid & 1;
    const int wn0  = (wid >> 1) * 40;      // 0 or 40

    const int oh0 = p0 / 56;
    const int abase = (oh0 * 58) & ~3;
    const int am0   = oh0 * 58 - abase;

    int pxr[5];
#pragma unroll
    for (int nf = 0; nf < 5; nf++) {
        int px = p0 + wn0 + nf * 8 + r;
        if (px >= HW) px = HW - 1;
        const int oh = px / 56, ow = px - oh * 56;
        pxr[nf] = oh * 58 + ow - oh0 * 58 + am0;
    }

    const uint32_t* xim = g_xh + (size_t)ni * (64 * PHW);

    float acc[4][5][4];
#pragma unroll
    for (int mf = 0; mf < 4; mf++)
#pragma unroll
        for (int nf = 0; nf < 5; nf++)
#pragma unroll
            for (int e = 0; e < 4; e++) acc[mf][nf][e] = 0.0f;

    // stage one chunk window: 32 rows x 74 cp16 = 2368 items -> 18.5/thread
    auto issueChunk = [&](int chunk) {
        const int cp0 = chunk * 32;
        const uint32_t dst = smb + (chunk * CHUNKW) * 4;
#pragma unroll
        for (int q = 0; q < 19; q++) {
            const int it = tid + q * 128;
            if (q == 18 && it >= 2368) break;
            const int row = it / WCOLS;
            const int col = it - row * WCOLS;
            cp16(dst + (row * LDW + col * 4) * 4,
                 xim + (size_t)(cp0 + row) * PHW + abase + col * 4);
        }
    };

    const uint32_t* wf0 = g_wf + ((size_t)oct * 2 + wmg) * 512 + lane * 16;
    auto loadA2 = [&](int P, uint32_t a[32]) {    // pair P -> kt16 2P, 2P+1
        const uint4* p  = reinterpret_cast<const uint4*>(wf0 + (size_t)(2 * P) * 2048);
        const uint4* p2 = reinterpret_cast<const uint4*>(wf0 + (size_t)(2 * P + 1) * 2048);
#pragma unroll
        for (int q = 0; q < 4; q++) {
            const uint4 v = p[q];
            a[q * 4 + 0] = v.x; a[q * 4 + 1] = v.y; a[q * 4 + 2] = v.z; a[q * 4 + 3] = v.w;
        }
#pragma unroll
        for (int q = 0; q < 4; q++) {
            const uint4 v = p2[q];
            a[16 + q * 4 + 0] = v.x; a[16 + q * 4 + 1] = v.y;
            a[16 + q * 4 + 2] = v.z; a[16 + q * 4 + 3] = v.w;
        }
    };

    issueChunk(0); CP_COMMIT;
    issueChunk(1); CP_COMMIT;

    uint32_t Ab[2][32];
    loadA2(0, Ab[0]);

#pragma unroll
    for (int chunk = 0; chunk < 2; chunk++) {
        if (chunk == 0) { CP_WAIT(1); } else { CP_WAIT(0); }
        __syncthreads();
        const uint32_t* win = smW + chunk * CHUNKW;

#pragma unroll 1
        for (int tap = 0; tap < 9; tap++) {
            const int rr = (tap * 86) >> 8;           // tap/3 for tap<9
            const int toff = rr * 58 + (tap - rr * 3);
#pragma unroll
            for (int sp = 0; sp < 2; sp++) {           // k16-pair within tap
                const int gpair = chunk * 18 + tap * 2 + sp;
                if (gpair + 1 < 36) loadA2(gpair + 1, Ab[sp ^ 1]);
#pragma unroll
                for (int h2 = 0; h2 < 2; h2++) {       // k16 within pair
                    const int hrow = (sp * 2 + h2) * 8;
                    uint32_t b[5][2];
#pragma unroll
                    for (int nf = 0; nf < 5; nf++) {
                        b[nf][0] = win[(hrow + cq) * LDW + toff + pxr[nf]];
                        b[nf][1] = win[(hrow + cq + 4) * LDW + toff + pxr[nf]];
                    }
                    const uint32_t* af = Ab[sp] + h2 * 16;
#pragma unroll
                    for (int mf = 0; mf < 4; mf++)
#pragma unroll
                        for (int nf = 0; nf < 5; nf++)
                            MMA16(acc[mf][nf], af + mf * 4, b[nf][0], b[nf][1]);
                }
            }
        }
    }

    const size_t obase = (size_t)ni * COUT * HW;
#pragma unroll
    for (int mf = 0; mf < 4; mf++) {
        const int mg = oct * 128 + wmg * 64 + mf * 16 + r;
        const float b0 = __ldg(bias + mg);
        const float b1 = __ldg(bias + mg + 8);
        float* o0 = out + obase + (size_t)mg * HW;
#pragma unroll
        for (int nf = 0; nf < 5; nf++) {
            const int px = p0 + wn0 + nf * 8 + cq * 2;
            if (px < HW) {
                float2 v0 = make_float2(acc[mf][nf][0] + b0, acc[mf][nf][1] + b0);
                float2 v1 = make_float2(acc[mf][nf][2] + b1, acc[mf][nf][3] + b1);
                *reinterpret_cast<float2*>(o0 + px) = v0;
                *reinterpret_cast<float2*>(o0 + (size_t)8 * HW + px) = v1;
            }
        }
    }
}

extern "C" void kernel_launch(void* const* d_in, const int* in_sizes, int n_in,
                              void* d_out, int out_size)
{
    const float* x    = (const float*)d_in[0];
    const float* W    = (const float*)d_in[1];
    const float* bias = (const float*)d_in[2];
    float* out        = (float*)d_out;

    static void* xh_addr = nullptr;
    if (!xh_addr) {
        cudaFuncSetAttribute(conv_mma, cudaFuncAttributeMaxDynamicSharedMemorySize,
                             SMEM_BYTES);
        cudaGetSymbolAddress(&xh_addr, g_xh);
    }

    cudaMemsetAsync(xh_addr, 0, sizeof(uint32_t) * (32 * 64 * PHW + 1024));
    prep_kernel<<<WF_BLOCKS + XH_BLOCKS, 256>>>(W, x);

    dim3 grid(40, 32, 2);   // ceil(3136/80)=40 px-tiles x 32 img x 2 oc-halves
    conv_mma<<<grid, 128, SMEM_BYTES>>>(bias, out);
}

// round 17
// speedup vs baseline: 1.2201x; 1.2201x over previous
#include <cuda_runtime.h>
#include <cuda_fp16.h>
#include <cstdint>

// Conv2d 3x3 s1 p1 via mma.sync m16n8k16 FP16 (f32 accum) implicit GEMM.
// 128-thread CTAs, CTA tile 128oc x 160px, 4 warps of 64x80 (4mf x 10nf)
// -> ~115 L1 bytes per MMA (vs 128 at 64x64). K order: chunk(64ch), tap, k16;
// per chunk one union window (32 cpairs x 356 words, stride 360) staged once
// via cp.async; both chunks staged upfront; 2 syncs per CTA.

#define HW    3136
#define PHW   3364            // 58*58
#define CIN   128
#define COUT  256
#define KTOT  1152
#define LDW   360             // window row stride (words); 360 mod 32 = 8
#define WCOLS 89              // cp16 per staged row (356 words)
#define CHUNKW (32*LDW)       // 11520 words per chunk window
#define SMEM_BYTES ((2*CHUNKW + 16)*4)   // 92224 B (x2 CTAs = 184.4KB/SM)

#define WF_WORDS  (72*2*2*32*16)         // 147456
#define WF_BLOCKS (WF_WORDS/256)         // 576
#define XH_ITEMS  (32*64*56*14)
#define XH_BLOCKS (XH_ITEMS/256)         // 6272

__device__ __align__(16) uint32_t g_wf[WF_WORDS];
__device__ __align__(16) uint32_t g_xh[32 * 64 * PHW + 1024];

// wf word w: reg=w&3, mf=(w>>2)&3, lane=(w>>4)&31, wmg=(w>>9)&1, oct=(w>>10)&1,
//            kt16=w>>11 ; kt16 = chunk*36 + tap*4 + h ; c = chunk*64+h*16+klocal
__global__ void prep_kernel(const float* __restrict__ W, const float* __restrict__ x) {
    if (blockIdx.x < WF_BLOCKS) {
        const int w = blockIdx.x * 256 + threadIdx.x;
        const int reg = w & 3, mf = (w >> 2) & 3, lane = (w >> 4) & 31;
        const int wmg = (w >> 9) & 1, oct = (w >> 10) & 1, kt = w >> 11;
        const int chunk = kt / 36, rem = kt - chunk * 36;
        const int tap = rem >> 2, h = rem & 3;
        const int r = lane >> 2, cq = lane & 3;
        const int oc = oct * 128 + wmg * 64 + mf * 16 + r + (reg & 1) * 8;
        const int klocal = 2 * cq + ((reg & 2) ? 8 : 0);
        const int c = chunk * 64 + h * 16 + klocal;
        const __half2 hv = __floats2half2_rn(W[oc * KTOT + c * 9 + tap],
                                             W[oc * KTOT + (c + 1) * 9 + tap]);
        g_wf[w] = *reinterpret_cast<const uint32_t*>(&hv);
    } else {
        const int item = (blockIdx.x - WF_BLOCKS) * 256 + threadIdx.x;
        const int g = item % 14;
        const int t = item / 14;
        const int ph = t % 56;
        const int cpni = t / 56;
        const float* src = x + (size_t)2 * cpni * HW + ph * 56 + 4 * g;
        const float4 lo = __ldg(reinterpret_cast<const float4*>(src));
        const float4 hi = __ldg(reinterpret_cast<const float4*>(src + HW));
        uint32_t* dst = g_xh + (size_t)cpni * PHW + (ph + 1) * 58 + 1 + 4 * g;
        __half2 h0 = __floats2half2_rn(lo.x, hi.x);
        __half2 h1 = __floats2half2_rn(lo.y, hi.y);
        __half2 h2 = __floats2half2_rn(lo.z, hi.z);
        __half2 h3 = __floats2half2_rn(lo.w, hi.w);
        dst[0] = *reinterpret_cast<const uint32_t*>(&h0);
        dst[1] = *reinterpret_cast<const uint32_t*>(&h1);
        dst[2] = *reinterpret_cast<const uint32_t*>(&h2);
        dst[3] = *reinterpret_cast<const uint32_t*>(&h3);
    }
}

__device__ __forceinline__ void cp16(uint32_t d, const void* s) {
    asm volatile("cp.async.cg.shared.global [%0], [%1], 16;" :: "r"(d), "l"(s));
}
#define CP_COMMIT asm volatile("cp.async.commit_group;" ::: "memory")
#define CP_WAIT(n) asm volatile("cp.async.wait_group %0;" :: "n"(n) : "memory")

#define MMA16(acc, a, b0, b1) \
    asm volatile("mma.sync.aligned.m16n8k16.row.col.f32.f16.f16.f32 " \
        "{%0,%1,%2,%3}, {%4,%5,%6,%7}, {%8,%9}, {%0,%1,%2,%3};" \
        : "+f"((acc)[0]), "+f"((acc)[1]), "+f"((acc)[2]), "+f"((acc)[3]) \
        : "r"((a)[0]), "r"((a)[1]), "r"((a)[2]), "r"((a)[3]), "r"(b0), "r"(b1))

__global__ void __launch_bounds__(128, 2)
conv_mma(const float* __restrict__ bias, float* __restrict__ out)
{
    extern __shared__ uint32_t smW[];
    const uint32_t smb = (uint32_t)__cvta_generic_to_shared(smW);
    const int tid  = threadIdx.x;
    const int lane = tid & 31;
    const int wid  = tid >> 5;
    const int r    = lane >> 2, cq = lane & 3;
    const int p0   = blockIdx.x * 160;     // 160-px tile
    const int ni   = blockIdx.y;
    const int oct  = blockIdx.z;
    const int wmg  = wid & 1;
    const int wn0  = (wid >> 1) * 80;      // 0 or 80

    const int oh0 = p0 / 56;
    const int abase = (oh0 * 58) & ~3;
    const int am0   = oh0 * 58 - abase;

    int pxr[10];
#pragma unroll
    for (int nf = 0; nf < 10; nf++) {
        int px = p0 + wn0 + nf * 8 + r;
        if (px >= HW) px = HW - 1;
        const int oh = px / 56, ow = px - oh * 56;
        pxr[nf] = oh * 58 + ow - oh0 * 58 + am0;
    }

    const uint32_t* xim = g_xh + (size_t)ni * (64 * PHW);

    float acc[4][10][4];
#pragma unroll
    for (int mf = 0; mf < 4; mf++)
#pragma unroll
        for (int nf = 0; nf < 10; nf++)
#pragma unroll
            for (int e = 0; e < 4; e++) acc[mf][nf][e] = 0.0f;

    // stage one chunk window: 32 rows x 89 cp16 = 2848 items
    auto issueChunk = [&](int chunk) {
        const int cp0 = chunk * 32;
        const uint32_t dst = smb + (chunk * CHUNKW) * 4;
#pragma unroll
        for (int q = 0; q < 23; q++) {
            const int it = tid + q * 128;
            if (q == 22 && it >= 2848) break;
            const int row = it / WCOLS;
            const int col = it - row * WCOLS;
            cp16(dst + (row * LDW + col * 4) * 4,
                 xim + (size_t)(cp0 + row) * PHW + abase + col * 4);
        }
    };

    const uint32_t* wf0 = g_wf + ((size_t)oct * 2 + wmg) * 512 + lane * 16;
    auto loadA = [&](int kt16, uint32_t a[16]) {
        const uint4* p = reinterpret_cast<const uint4*>(wf0 + (size_t)kt16 * 2048);
#pragma unroll
        for (int q = 0; q < 4; q++) {
            const uint4 v = p[q];
            a[q * 4 + 0] = v.x; a[q * 4 + 1] = v.y;
            a[q * 4 + 2] = v.z; a[q * 4 + 3] = v.w;
        }
    };

    issueChunk(0); CP_COMMIT;
    issueChunk(1); CP_COMMIT;

#pragma unroll
    for (int chunk = 0; chunk < 2; chunk++) {
        if (chunk == 0) { CP_WAIT(1); } else { CP_WAIT(0); }
        __syncthreads();
        const uint32_t* win = smW + chunk * CHUNKW;

#pragma unroll 1
        for (int tap = 0; tap < 9; tap++) {
            const int rr = (tap * 86) >> 8;           // tap/3 for tap<9
            const int toff = rr * 58 + (tap - rr * 3);
#pragma unroll
            for (int h = 0; h < 4; h++) {             // k16 within tap
                uint32_t A[16];
                loadA(chunk * 36 + tap * 4 + h, A);
                const int hrow = h * 8;
                uint32_t b[10][2];
#pragma unroll
                for (int nf = 0; nf < 10; nf++) {
                    b[nf][0] = win[(hrow + cq) * LDW + toff + pxr[nf]];
                    b[nf][1] = win[(hrow + cq + 4) * LDW + toff + pxr[nf]];
                }
#pragma unroll
                for (int mf = 0; mf < 4; mf++)
#pragma unroll
                    for (int nf = 0; nf < 10; nf++)
                        MMA16(acc[mf][nf], A + mf * 4, b[nf][0], b[nf][1]);
            }
        }
    }

    const size_t obase = (size_t)ni * COUT * HW;
#pragma unroll
    for (int mf = 0; mf < 4; mf++) {
        const int mg = oct * 128 + wmg * 64 + mf * 16 + r;
        const float b0 = __ldg(bias + mg);
        const float b1 = __ldg(bias + mg + 8);
        float* o0 = out + obase + (size_t)mg * HW;
#pragma unroll
        for (int nf = 0; nf < 10; nf++) {
            const int px = p0 + wn0 + nf * 8 + cq * 2;
            if (px < HW) {
                float2 v0 = make_float2(acc[mf][nf][0] + b0, acc[mf][nf][1] + b0);
                float2 v1 = make_float2(acc[mf][nf][2] + b1, acc[mf][nf][3] + b1);
                *reinterpret_cast<float2*>(o0 + px) = v0;
                *reinterpret_cast<float2*>(o0 + (size_t)8 * HW + px) = v1;
            }
        }
    }
}

extern "C" void kernel_launch(void* const* d_in, const int* in_sizes, int n_in,
                              void* d_out, int out_size)
{
    const float* x    = (const float*)d_in[0];
    const float* W    = (const float*)d_in[1];
    const float* bias = (const float*)d_in[2];
    float* out        = (float*)d_out;

    static void* xh_addr = nullptr;
    if (!xh_addr) {
        cudaFuncSetAttribute(conv_mma, cudaFuncAttributeMaxDynamicSharedMemorySize,
                             SMEM_BYTES);
        cudaGetSymbolAddress(&xh_addr, g_xh);
    }

    cudaMemsetAsync(xh_addr, 0, sizeof(uint32_t) * (32 * 64 * PHW + 1024));
    prep_kernel<<<WF_BLOCKS + XH_BLOCKS, 256>>>(W, x);

    dim3 grid(20, 32, 2);   // 20 px-tiles (160 px) x 32 img x 2 oc-halves
    conv_mma<<<grid, 128, SMEM_BYTES>>>(bias, out);
}